// round 11
// baseline (speedup 1.0000x reference)
#include <cuda_runtime.h>
#include <math.h>

#define NUM_HEADS    32
#define HEAD_SIZE    128
#define NUM_KV_HEADS 8
#define GRP          4
#define BLK_SZ       16
#define MAX_BLOCKS   64
#define MAX_CTX      1024
#define NUM_SEQS     64
#define SCALE        0.08838834764831845f
#define LOG2E        1.4426950408889634f

#define PART         128                  // tokens per split-K partition
#define MAXP         (MAX_CTX / PART)     // 8
#define PBLK         (PART / BLK_SZ)      // 8 blocks per partition

// split-K scratch (device globals: no allocation allowed)
__device__ float g_po[NUM_SEQS * NUM_KV_HEADS * MAXP * GRP * HEAD_SIZE]; // 8 MB
__device__ float g_pm[NUM_SEQS * NUM_KV_HEADS * MAXP * GRP];
__device__ float g_ps[NUM_SEQS * NUM_KV_HEADS * MAXP * GRP];
__device__ int   g_cnt[NUM_SEQS * NUM_KV_HEADS];   // zero-init; self-resetting

__device__ __forceinline__ float4 ldcs4(const float* p) {
    return __ldcs((const float4*)p);
}
__device__ __forceinline__ void prefetch_l2(const float* p) {
    asm volatile("prefetch.global.L2 [%0];" :: "l"(p));
}

__global__ __launch_bounds__(256, 4)
void paged_attn_split(const float* __restrict__ q_in,
                      const float* __restrict__ knew,
                      const float* __restrict__ vnew,
                      const float* __restrict__ kcache,
                      const float* __restrict__ vcache,
                      const int*   __restrict__ btab,
                      const int*   __restrict__ ctxlen,
                      float*       __restrict__ out)
{
    const int bx = blockIdx.x;
    const int s  = bx >> 6;              // sequence
    const int h  = (bx >> 3) & 7;        // kv head
    const int p  = bx & 7;               // partition
    const int sh = (s << 3) | h;

    const int L  = ctxlen[s];
    const int t0 = p * PART;
    if (t0 >= L) return;
    const int np   = (L + PART - 1) / PART;
    const int t1   = min(L, t0 + PART);
    const int n    = t1 - t0;
    const int nblk = (n + BLK_SZ - 1) / BLK_SZ;     // 1..8
    const int npad = nblk * BLK_SZ;

    const int tid  = threadIdx.x;
    const int lane = tid & 31;
    const int wid  = tid >> 5;

    __shared__ float sh_q[GRP][HEAD_SIZE];       // 2 KB
    __shared__ float sh_p[GRP][PART];            // 2 KB
    __shared__ float sh_acc[GRP][HEAD_SIZE];     // 2 KB
    __shared__ float sh_m[GRP], sh_s[GRP];
    __shared__ float sh_w[MAXP][GRP];
    __shared__ int   sh_btab[PBLK];
    __shared__ int   sh_win;

    if (tid < PBLK) sh_btab[tid] = btab[s * MAX_BLOCKS + p * PBLK + tid];
    for (int i = tid; i < GRP * HEAD_SIZE; i += 256) {
        int g = i >> 7, d = i & 127;
        sh_q[g][d] = q_in[(size_t)s * (NUM_HEADS * HEAD_SIZE) + (h * GRP + g) * HEAD_SIZE + d];
    }
    __syncthreads();

    // ---- V prefetch to L2: every warp covers its (clamped) block's full 8 KB.
    //      128B-line coverage: float offsets lane*32 and 1024 + lane*32.
    {
        const int bc = min(wid, nblk - 1);
        const float* vblk = vcache + ((size_t)sh_btab[bc] * NUM_KV_HEADS + h) * 2048;
        prefetch_l2(vblk + lane * 32);
        prefetch_l2(vblk + 1024 + lane * 32);
    }

    // ---- Phase 1: warp per 16-token block scores K (coalesced LDG) ----
    if (wid < nblk) {
        const int tb   = lane & 15;
        const int half = lane >> 4;
        const int pb   = sh_btab[wid];
        const int t    = t0 + wid * BLK_SZ + tb;
        const int lt   = wid * BLK_SZ + tb;

        const float* kb;
        int cs;
        if (t == L - 1) {
            kb = knew + (size_t)s * (NUM_KV_HEADS * HEAD_SIZE) + h * HEAD_SIZE + half * 64;
            cs = 8;
        } else {
            kb = kcache + ((size_t)pb * NUM_KV_HEADS + h) * 2048 + (size_t)half * 1024 + tb * 8;
            cs = 128;
        }

        float acc[GRP] = {0.f, 0.f, 0.f, 0.f};
        #pragma unroll
        for (int j = 0; j < 8; j++) {
            float4 k0 = ldcs4(kb + j * cs);
            float4 k1 = ldcs4(kb + j * cs + 4);
            int d0 = half * 64 + j * 8;
            #pragma unroll
            for (int g = 0; g < GRP; g++) {
                float4 qa = *(const float4*)&sh_q[g][d0];
                float4 qb = *(const float4*)&sh_q[g][d0 + 4];
                acc[g] += k0.x * qa.x + k0.y * qa.y + k0.z * qa.z + k0.w * qa.w
                        + k1.x * qb.x + k1.y * qb.y + k1.z * qb.z + k1.w * qb.w;
            }
        }
        #pragma unroll
        for (int g = 0; g < GRP; g++)
            acc[g] += __shfl_xor_sync(0xffffffffu, acc[g], 16);

        if (half == 0) {
            #pragma unroll
            for (int g = 0; g < GRP; g++)
                sh_p[g][lt] = (lt < n) ? acc[g] * SCALE : -1e30f;
        }
    } else {
        // zero-pad probabilities for inactive blocks (phase 3 runs fixed 8 blocks)
        const int tb = lane & 15;
        if (lane < 16) {
            const int lt = wid * BLK_SZ + tb;
            #pragma unroll
            for (int g = 0; g < GRP; g++) sh_p[g][lt] = 0.f;
        }
    }
    __syncthreads();

    // ---- Phase 2: local softmax stats (4 warps, one head each) ----
    if (wid < GRP) {
        const int g = wid;
        float m = -1e30f;
        for (int i = lane; i < npad; i += 32) m = fmaxf(m, sh_p[g][i]);
        #pragma unroll
        for (int o = 16; o > 0; o >>= 1) m = fmaxf(m, __shfl_xor_sync(0xffffffffu, m, o));
        float sum = 0.f;
        for (int i = lane; i < npad; i += 32) {
            float e = exp2f((sh_p[g][i] - m) * LOG2E);
            sh_p[g][i] = e;
            sum += e;
        }
        #pragma unroll
        for (int o = 16; o > 0; o >>= 1) sum += __shfl_xor_sync(0xffffffffu, sum, o);
        if (lane == 0) { sh_m[g] = m; sh_s[g] = sum; }
    }
    __syncthreads();

    // ---- Phase 3: partial P@V, fully coalesced; V now L2-resident.
    //      lane = (j = token quad, d-low); warp covers 8 consecutive d x 4 quads.
    {
        const int j  = lane & 3;
        const int d0 = (wid << 3) + (lane >> 2);     // 0..63
        const int d1 = d0 + 64;
        const float vnd0 = vnew[(size_t)s * (NUM_KV_HEADS * HEAD_SIZE) + h * HEAD_SIZE + d0];
        const float vnd1 = vnew[(size_t)s * (NUM_KV_HEADS * HEAD_SIZE) + h * HEAD_SIZE + d1];

        float acc0[GRP] = {0.f, 0.f, 0.f, 0.f};
        float acc1[GRP] = {0.f, 0.f, 0.f, 0.f};
        #pragma unroll
        for (int b = 0; b < PBLK; b++) {
            const int bc = min(b, nblk - 1);          // clamp: sh_p is zero there
            const float* vb = vcache + ((size_t)sh_btab[bc] * NUM_KV_HEADS + h) * 2048;
            float4 v0 = ldcs4(vb + d0 * 16 + j * 4);
            float4 v1 = ldcs4(vb + d1 * 16 + j * 4);
            const int ltj = b * BLK_SZ + j * 4;
            const int o = (L - 1) - (t0 + ltj);       // new-token value override
            if ((unsigned)o < 4u) {
                if      (o == 0) { v0.x = vnd0; v1.x = vnd1; }
                else if (o == 1) { v0.y = vnd0; v1.y = vnd1; }
                else if (o == 2) { v0.z = vnd0; v1.z = vnd1; }
                else             { v0.w = vnd0; v1.w = vnd1; }
            }
            #pragma unroll
            for (int g = 0; g < GRP; g++) {
                float4 pr = *(const float4*)&sh_p[g][ltj];
                acc0[g] += v0.x * pr.x + v0.y * pr.y + v0.z * pr.z + v0.w * pr.w;
                acc1[g] += v1.x * pr.x + v1.y * pr.y + v1.z * pr.z + v1.w * pr.w;
            }
        }
        // reduce over token quads (lane bits 0-1)
        #pragma unroll
        for (int g = 0; g < GRP; g++) {
            acc0[g] += __shfl_xor_sync(0xffffffffu, acc0[g], 1);
            acc0[g] += __shfl_xor_sync(0xffffffffu, acc0[g], 2);
            acc1[g] += __shfl_xor_sync(0xffffffffu, acc1[g], 1);
            acc1[g] += __shfl_xor_sync(0xffffffffu, acc1[g], 2);
        }
        if (j == 0) {
            #pragma unroll
            for (int g = 0; g < GRP; g++) {
                sh_acc[g][d0] = acc0[g];
                sh_acc[g][d1] = acc1[g];
            }
        }
    }
    __syncthreads();

    // ---- write partials ----
    const size_t base = ((size_t)bx) * (GRP * HEAD_SIZE);
    for (int i = tid; i < GRP * HEAD_SIZE; i += 256)
        g_po[base + i] = sh_acc[i >> 7][i & 127];
    if (tid < GRP) {
        g_pm[(size_t)bx * GRP + tid] = sh_m[tid];
        g_ps[(size_t)bx * GRP + tid] = sh_s[tid];
    }

    // ---- fused combine: last CTA for (s,h) finalizes ----
    __threadfence();
    if (tid == 0) {
        int old = atomicAdd(&g_cnt[sh], 1);
        sh_win = (old == np - 1);
        if (sh_win) g_cnt[sh] = 0;   // self-reset for graph replay
    }
    __syncthreads();
    if (!sh_win) return;
    __threadfence();                  // acquire: see all partitions' partials

    // one warp computes combine weights: lane = g + 4*pp
    if (wid == 0) {
        const int g  = lane & 3;
        const int pp = lane >> 2;
        const bool act = (pp < np);
        const size_t idx = ((size_t)sh * MAXP + pp) * GRP + g;
        float m  = act ? g_pm[idx] : -1e30f;
        float M = m;
        #pragma unroll
        for (int o = 4; o < 32; o <<= 1) M = fmaxf(M, __shfl_xor_sync(0xffffffffu, M, o));
        float w  = act ? exp2f((m - M) * LOG2E) : 0.f;
        float den = act ? w * g_ps[idx] : 0.f;
        #pragma unroll
        for (int o = 4; o < 32; o <<= 1) den += __shfl_xor_sync(0xffffffffu, den, o);
        sh_w[pp][g] = w / den;
    }
    __syncthreads();

    for (int i = tid; i < GRP * HEAD_SIZE; i += 256) {
        const int g = i >> 7, d = i & 127;
        float acc = 0.f;
        for (int pp = 0; pp < np; pp++)
            acc += sh_w[pp][g] * g_po[((size_t)sh * MAXP + pp) * (GRP * HEAD_SIZE) + i];
        out[(size_t)s * (NUM_HEADS * HEAD_SIZE) + (h * GRP + g) * HEAD_SIZE + d] = acc;
    }
}

extern "C" void kernel_launch(void* const* d_in, const int* in_sizes, int n_in,
                              void* d_out, int out_size)
{
    const float* query       = (const float*)d_in[0];
    const float* key         = (const float*)d_in[1];
    const float* value       = (const float*)d_in[2];
    const float* key_cache   = (const float*)d_in[3];
    const float* value_cache = (const float*)d_in[4];
    const int*   block_tab   = (const int*)d_in[5];
    const int*   ctx_lens    = (const int*)d_in[6];
    float* out = (float*)d_out;

    paged_attn_split<<<NUM_SEQS * NUM_KV_HEADS * MAXP, 256>>>(
        query, key, value, key_cache, value_cache, block_tab, ctx_lens, out);
}

// round 12
// speedup vs baseline: 1.0773x; 1.0773x over previous
#include <cuda_runtime.h>
#include <math.h>

#define NUM_HEADS    32
#define HEAD_SIZE    128
#define NUM_KV_HEADS 8
#define GRP          4
#define BLK_SZ       16
#define MAX_BLOCKS   64
#define MAX_CTX      1024
#define NUM_SEQS     64
#define SCALE        0.08838834764831845f
#define LOG2E        1.4426950408889634f

#define PART         128                  // tokens per split-K partition
#define MAXP         (MAX_CTX / PART)     // 8
#define PBLK         (PART / BLK_SZ)      // 8 blocks per partition
#define NTHR         128

// split-K scratch (device globals: no allocation allowed)
__device__ float g_po[NUM_SEQS * NUM_KV_HEADS * MAXP * GRP * HEAD_SIZE]; // 8 MB
__device__ float g_pm[NUM_SEQS * NUM_KV_HEADS * MAXP * GRP];
__device__ float g_ps[NUM_SEQS * NUM_KV_HEADS * MAXP * GRP];
__device__ int   g_cnt[NUM_SEQS * NUM_KV_HEADS];   // zero-init; self-resetting

__device__ __forceinline__ float4 ldcs4(const float* p) {
    return __ldcs((const float4*)p);
}

__global__ __launch_bounds__(NTHR, 8)
void paged_attn_split(const float* __restrict__ q_in,
                      const float* __restrict__ knew,
                      const float* __restrict__ vnew,
                      const float* __restrict__ kcache,
                      const float* __restrict__ vcache,
                      const int*   __restrict__ btab,
                      const int*   __restrict__ ctxlen,
                      float*       __restrict__ out)
{
    const int bx = blockIdx.x;
    const int s  = bx >> 6;              // sequence
    const int h  = (bx >> 3) & 7;        // kv head
    const int p  = bx & 7;               // partition
    const int sh = (s << 3) | h;

    const int L  = ctxlen[s];
    const int t0 = p * PART;
    if (t0 >= L) return;
    const int np   = (L + PART - 1) / PART;
    const int t1   = min(L, t0 + PART);
    const int n    = t1 - t0;
    const int nblk = (n + BLK_SZ - 1) / BLK_SZ;     // 1..8
    const int npad = nblk * BLK_SZ;

    const int tid  = threadIdx.x;
    const int lane = tid & 31;
    const int wid  = tid >> 5;           // 4 warps

    __shared__ float sh_q[GRP][HEAD_SIZE];       // 2 KB
    __shared__ float sh_p[GRP][PART];            // 2 KB
    __shared__ float sh_acc[GRP][HEAD_SIZE];     // 2 KB
    __shared__ float sh_m[GRP], sh_s[GRP];
    __shared__ float sh_w[MAXP][GRP];
    __shared__ int   sh_btab[PBLK];
    __shared__ int   sh_win;

    if (tid < PBLK) sh_btab[tid] = btab[s * MAX_BLOCKS + p * PBLK + tid];
    for (int i = tid; i < GRP * HEAD_SIZE; i += NTHR) {
        int g = i >> 7, d = i & 127;
        sh_q[g][d] = q_in[(size_t)s * (NUM_HEADS * HEAD_SIZE) + (h * GRP + g) * HEAD_SIZE + d];
    }
    __syncthreads();

    // ---- Phase 1: warp wid scores blocks wid and wid+4, interleaved ----
    {
        const int tb   = lane & 15;
        const int half = lane >> 4;
        const int bA = wid, bB = wid + 4;
        const bool vA = (bA < nblk), vB = (bB < nblk);
        const int pbA = sh_btab[min(bA, nblk - 1)];
        const int pbB = sh_btab[min(bB, nblk - 1)];
        const int tA = t0 + bA * BLK_SZ + tb;
        const int tB = t0 + bB * BLK_SZ + tb;

        const float* kbA; int csA;
        if (tA == L - 1) {   // only possible when bA < nblk
            kbA = knew + (size_t)s * (NUM_KV_HEADS * HEAD_SIZE) + h * HEAD_SIZE + half * 64;
            csA = 8;
        } else {
            kbA = kcache + ((size_t)pbA * NUM_KV_HEADS + h) * 2048 + (size_t)half * 1024 + tb * 8;
            csA = 128;
        }
        const float* kbB; int csB;
        if (tB == L - 1) {
            kbB = knew + (size_t)s * (NUM_KV_HEADS * HEAD_SIZE) + h * HEAD_SIZE + half * 64;
            csB = 8;
        } else {
            kbB = kcache + ((size_t)pbB * NUM_KV_HEADS + h) * 2048 + (size_t)half * 1024 + tb * 8;
            csB = 128;
        }

        float aA[GRP] = {0.f, 0.f, 0.f, 0.f};
        float aB[GRP] = {0.f, 0.f, 0.f, 0.f};
        #pragma unroll
        for (int j = 0; j < 8; j++) {
            float4 kA0 = ldcs4(kbA + j * csA);
            float4 kA1 = ldcs4(kbA + j * csA + 4);
            float4 kB0 = ldcs4(kbB + j * csB);
            float4 kB1 = ldcs4(kbB + j * csB + 4);
            int d0 = half * 64 + j * 8;
            #pragma unroll
            for (int g = 0; g < GRP; g++) {
                float4 qa = *(const float4*)&sh_q[g][d0];
                float4 qb = *(const float4*)&sh_q[g][d0 + 4];
                aA[g] += kA0.x * qa.x + kA0.y * qa.y + kA0.z * qa.z + kA0.w * qa.w
                       + kA1.x * qb.x + kA1.y * qb.y + kA1.z * qb.z + kA1.w * qb.w;
                aB[g] += kB0.x * qa.x + kB0.y * qa.y + kB0.z * qa.z + kB0.w * qa.w
                       + kB1.x * qb.x + kB1.y * qb.y + kB1.z * qb.z + kB1.w * qb.w;
            }
        }
        #pragma unroll
        for (int g = 0; g < GRP; g++) {
            aA[g] += __shfl_xor_sync(0xffffffffu, aA[g], 16);
            aB[g] += __shfl_xor_sync(0xffffffffu, aB[g], 16);
        }

        if (half == 0) {
            const int ltA = bA * BLK_SZ + tb;
            const int ltB = bB * BLK_SZ + tb;
            #pragma unroll
            for (int g = 0; g < GRP; g++) {
                sh_p[g][ltA] = vA ? ((ltA < n) ? aA[g] * SCALE : -1e30f) : 0.f;
                sh_p[g][ltB] = vB ? ((ltB < n) ? aB[g] * SCALE : -1e30f) : 0.f;
            }
        }
    }
    __syncthreads();

    // ---- Phase 2: local softmax stats (4 warps, one head each) ----
    {
        const int g = wid;
        float m = -1e30f;
        for (int i = lane; i < npad; i += 32) m = fmaxf(m, sh_p[g][i]);
        #pragma unroll
        for (int o = 16; o > 0; o >>= 1) m = fmaxf(m, __shfl_xor_sync(0xffffffffu, m, o));
        float sum = 0.f;
        for (int i = lane; i < npad; i += 32) {
            float e = exp2f((sh_p[g][i] - m) * LOG2E);
            sh_p[g][i] = e;
            sum += e;
        }
        #pragma unroll
        for (int o = 16; o > 0; o >>= 1) sum += __shfl_xor_sync(0xffffffffu, sum, o);
        if (lane == 0) { sh_m[g] = m; sh_s[g] = sum; }
    }
    __syncthreads();

    // ---- Phase 3: partial P@V, fully coalesced. Two d-group passes per warp.
    //      lane = (j = token quad, d-low); warp covers 8 consecutive d x 4 quads.
    {
        const int j     = lane & 3;
        const int dbase = (wid << 3) + (lane >> 2);      // 0..31
        #pragma unroll
        for (int hh = 0; hh < 2; hh++) {
            const int d0 = dbase + hh * 32;              // 0..63
            const int d1 = d0 + 64;
            const float vnd0 = vnew[(size_t)s * (NUM_KV_HEADS * HEAD_SIZE) + h * HEAD_SIZE + d0];
            const float vnd1 = vnew[(size_t)s * (NUM_KV_HEADS * HEAD_SIZE) + h * HEAD_SIZE + d1];

            float acc0[GRP] = {0.f, 0.f, 0.f, 0.f};
            float acc1[GRP] = {0.f, 0.f, 0.f, 0.f};
            #pragma unroll
            for (int b = 0; b < PBLK; b++) {
                const int bc = min(b, nblk - 1);          // clamp: sh_p is zero there
                const float* vb = vcache + ((size_t)sh_btab[bc] * NUM_KV_HEADS + h) * 2048;
                float4 v0 = ldcs4(vb + d0 * 16 + j * 4);
                float4 v1 = ldcs4(vb + d1 * 16 + j * 4);
                const int ltj = b * BLK_SZ + j * 4;
                const int o = (L - 1) - (t0 + ltj);       // new-token value override
                if ((unsigned)o < 4u) {
                    if      (o == 0) { v0.x = vnd0; v1.x = vnd1; }
                    else if (o == 1) { v0.y = vnd0; v1.y = vnd1; }
                    else if (o == 2) { v0.z = vnd0; v1.z = vnd1; }
                    else             { v0.w = vnd0; v1.w = vnd1; }
                }
                #pragma unroll
                for (int g = 0; g < GRP; g++) {
                    float4 pr = *(const float4*)&sh_p[g][ltj];
                    acc0[g] += v0.x * pr.x + v0.y * pr.y + v0.z * pr.z + v0.w * pr.w;
                    acc1[g] += v1.x * pr.x + v1.y * pr.y + v1.z * pr.z + v1.w * pr.w;
                }
            }
            // reduce over token quads (lane bits 0-1)
            #pragma unroll
            for (int g = 0; g < GRP; g++) {
                acc0[g] += __shfl_xor_sync(0xffffffffu, acc0[g], 1);
                acc0[g] += __shfl_xor_sync(0xffffffffu, acc0[g], 2);
                acc1[g] += __shfl_xor_sync(0xffffffffu, acc1[g], 1);
                acc1[g] += __shfl_xor_sync(0xffffffffu, acc1[g], 2);
            }
            if (j == 0) {
                #pragma unroll
                for (int g = 0; g < GRP; g++) {
                    sh_acc[g][d0] = acc0[g];
                    sh_acc[g][d1] = acc1[g];
                }
            }
        }
    }
    __syncthreads();

    // ---- write partials ----
    const size_t base = ((size_t)bx) * (GRP * HEAD_SIZE);
    for (int i = tid; i < GRP * HEAD_SIZE; i += NTHR)
        g_po[base + i] = sh_acc[i >> 7][i & 127];
    if (tid < GRP) {
        g_pm[(size_t)bx * GRP + tid] = sh_m[tid];
        g_ps[(size_t)bx * GRP + tid] = sh_s[tid];
    }

    // ---- fused combine: last CTA for (s,h) finalizes ----
    __threadfence();
    if (tid == 0) {
        int old = atomicAdd(&g_cnt[sh], 1);
        sh_win = (old == np - 1);
        if (sh_win) g_cnt[sh] = 0;   // self-reset for graph replay
    }
    __syncthreads();
    if (!sh_win) return;
    __threadfence();                  // acquire: see all partitions' partials

    // one warp computes combine weights: lane = g + 4*pp
    if (wid == 0) {
        const int g  = lane & 3;
        const int pp = lane >> 2;
        const bool act = (pp < np);
        const size_t idx = ((size_t)sh * MAXP + pp) * GRP + g;
        float m  = act ? g_pm[idx] : -1e30f;
        float M = m;
        #pragma unroll
        for (int o = 4; o < 32; o <<= 1) M = fmaxf(M, __shfl_xor_sync(0xffffffffu, M, o));
        float w  = act ? exp2f((m - M) * LOG2E) : 0.f;
        float den = act ? w * g_ps[idx] : 0.f;
        #pragma unroll
        for (int o = 4; o < 32; o <<= 1) den += __shfl_xor_sync(0xffffffffu, den, o);
        sh_w[pp][g] = w / den;
    }
    __syncthreads();

    for (int i = tid; i < GRP * HEAD_SIZE; i += NTHR) {
        const int g = i >> 7, d = i & 127;
        float acc = 0.f;
        for (int pp = 0; pp < np; pp++)
            acc += sh_w[pp][g] * g_po[((size_t)sh * MAXP + pp) * (GRP * HEAD_SIZE) + i];
        out[(size_t)s * (NUM_HEADS * HEAD_SIZE) + (h * GRP + g) * HEAD_SIZE + d] = acc;
    }
}

extern "C" void kernel_launch(void* const* d_in, const int* in_sizes, int n_in,
                              void* d_out, int out_size)
{
    const float* query       = (const float*)d_in[0];
    const float* key         = (const float*)d_in[1];
    const float* value       = (const float*)d_in[2];
    const float* key_cache   = (const float*)d_in[3];
    const float* value_cache = (const float*)d_in[4];
    const int*   block_tab   = (const int*)d_in[5];
    const int*   ctx_lens    = (const int*)d_in[6];
    float* out = (float*)d_out;

    paged_attn_split<<<NUM_SEQS * NUM_KV_HEADS * MAXP, NTHR>>>(
        query, key, value, key_cache, value_cache, block_tab, ctx_lens, out);
}

// round 13
// speedup vs baseline: 1.1383x; 1.0565x over previous
#include <cuda_runtime.h>
#include <math.h>

#define NUM_HEADS    32
#define HEAD_SIZE    128
#define NUM_KV_HEADS 8
#define GRP          4
#define BLK_SZ       16
#define MAX_BLOCKS   64
#define MAX_CTX      1024
#define NUM_SEQS     64
#define SCALE        0.08838834764831845f
#define LOG2E        1.4426950408889634f

#define PART         128                  // tokens per split-K partition
#define MAXP         (MAX_CTX / PART)     // 8
#define PBLK         (PART / BLK_SZ)      // 8 blocks per partition

// split-K scratch (device globals: no allocation allowed)
__device__ float g_po[NUM_SEQS * NUM_KV_HEADS * MAXP * GRP * HEAD_SIZE]; // 8 MB
__device__ float g_pm[NUM_SEQS * NUM_KV_HEADS * MAXP * GRP];
__device__ float g_ps[NUM_SEQS * NUM_KV_HEADS * MAXP * GRP];
__device__ int   g_cnt[NUM_SEQS * NUM_KV_HEADS];   // zero-init; self-resetting

__device__ __forceinline__ float4 ldcs4(const float* p) {
    return __ldcs((const float4*)p);
}

__global__ __launch_bounds__(256, 3)
void paged_attn_split(const float* __restrict__ q_in,
                      const float* __restrict__ knew,
                      const float* __restrict__ vnew,
                      const float* __restrict__ kcache,
                      const float* __restrict__ vcache,
                      const int*   __restrict__ btab,
                      const int*   __restrict__ ctxlen,
                      float*       __restrict__ out)
{
    const int bx = blockIdx.x;
    const int s  = bx >> 6;              // sequence
    const int h  = (bx >> 3) & 7;        // kv head
    const int p  = bx & 7;               // partition
    const int sh = (s << 3) | h;

    const int L  = ctxlen[s];
    const int t0 = p * PART;
    if (t0 >= L) return;
    const int np   = (L + PART - 1) / PART;
    const int t1   = min(L, t0 + PART);
    const int n    = t1 - t0;
    const int nblk = (n + BLK_SZ - 1) / BLK_SZ;     // 1..8
    const int npad = nblk * BLK_SZ;

    const int tid  = threadIdx.x;
    const int lane = tid & 31;
    const int wid  = tid >> 5;

    __shared__ float sh_q[GRP][HEAD_SIZE];       // 2 KB
    __shared__ float sh_p[GRP][PART];            // 2 KB
    __shared__ float sh_acc[GRP][HEAD_SIZE];     // 2 KB
    __shared__ float sh_m[GRP], sh_s[GRP];
    __shared__ float sh_w[MAXP][GRP];
    __shared__ int   sh_btab[PBLK];
    __shared__ int   sh_win;

    if (tid < PBLK) sh_btab[tid] = btab[s * MAX_BLOCKS + p * PBLK + tid];
    for (int i = tid; i < GRP * HEAD_SIZE; i += 256) {
        int g = i >> 7, d = i & 127;
        sh_q[g][d] = q_in[(size_t)s * (NUM_HEADS * HEAD_SIZE) + (h * GRP + g) * HEAD_SIZE + d];
    }
    __syncthreads();

    // ---- Phase 1: warp per 16-token block. Two passes; each pass stages 8
    //      independent LDG.128 before any FMA (deep MLP). ----
    if (wid < nblk) {
        const int tb   = lane & 15;
        const int half = lane >> 4;
        const int pb   = sh_btab[wid];
        const int t    = t0 + wid * BLK_SZ + tb;
        const int lt   = wid * BLK_SZ + tb;

        const float* kb;
        int cs;
        if (t == L - 1) {
            kb = knew + (size_t)s * (NUM_KV_HEADS * HEAD_SIZE) + h * HEAD_SIZE + half * 64;
            cs = 8;
        } else {
            kb = kcache + ((size_t)pb * NUM_KV_HEADS + h) * 2048 + (size_t)half * 1024 + tb * 8;
            cs = 128;
        }

        float acc[GRP] = {0.f, 0.f, 0.f, 0.f};

        // pass A: first float4 of each j
        {
            float4 ka[8];
            #pragma unroll
            for (int j = 0; j < 8; j++) ka[j] = ldcs4(kb + j * cs);
            #pragma unroll
            for (int j = 0; j < 8; j++) {
                const int d0 = half * 64 + j * 8;
                float4 qa = *(const float4*)&sh_q[0][d0];
                acc[0] += ka[j].x * qa.x + ka[j].y * qa.y + ka[j].z * qa.z + ka[j].w * qa.w;
                qa = *(const float4*)&sh_q[1][d0];
                acc[1] += ka[j].x * qa.x + ka[j].y * qa.y + ka[j].z * qa.z + ka[j].w * qa.w;
                qa = *(const float4*)&sh_q[2][d0];
                acc[2] += ka[j].x * qa.x + ka[j].y * qa.y + ka[j].z * qa.z + ka[j].w * qa.w;
                qa = *(const float4*)&sh_q[3][d0];
                acc[3] += ka[j].x * qa.x + ka[j].y * qa.y + ka[j].z * qa.z + ka[j].w * qa.w;
            }
        }
        // pass B: second float4 of each j
        {
            float4 kc[8];
            #pragma unroll
            for (int j = 0; j < 8; j++) kc[j] = ldcs4(kb + j * cs + 4);
            #pragma unroll
            for (int j = 0; j < 8; j++) {
                const int d0 = half * 64 + j * 8 + 4;
                float4 qa = *(const float4*)&sh_q[0][d0];
                acc[0] += kc[j].x * qa.x + kc[j].y * qa.y + kc[j].z * qa.z + kc[j].w * qa.w;
                qa = *(const float4*)&sh_q[1][d0];
                acc[1] += kc[j].x * qa.x + kc[j].y * qa.y + kc[j].z * qa.z + kc[j].w * qa.w;
                qa = *(const float4*)&sh_q[2][d0];
                acc[2] += kc[j].x * qa.x + kc[j].y * qa.y + kc[j].z * qa.z + kc[j].w * qa.w;
                qa = *(const float4*)&sh_q[3][d0];
                acc[3] += kc[j].x * qa.x + kc[j].y * qa.y + kc[j].z * qa.z + kc[j].w * qa.w;
            }
        }

        #pragma unroll
        for (int g = 0; g < GRP; g++)
            acc[g] += __shfl_xor_sync(0xffffffffu, acc[g], 16);

        if (half == 0) {
            #pragma unroll
            for (int g = 0; g < GRP; g++)
                sh_p[g][lt] = (lt < n) ? acc[g] * SCALE : -1e30f;
        }
    } else {
        // zero-pad probabilities for inactive blocks (phase 3 runs fixed 8 blocks)
        const int tb = lane & 15;
        if (lane < 16) {
            const int lt = wid * BLK_SZ + tb;
            #pragma unroll
            for (int g = 0; g < GRP; g++) sh_p[g][lt] = 0.f;
        }
    }
    __syncthreads();

    // ---- Phase 2: local softmax stats (4 warps, one head each) ----
    if (wid < GRP) {
        const int g = wid;
        float m = -1e30f;
        for (int i = lane; i < npad; i += 32) m = fmaxf(m, sh_p[g][i]);
        #pragma unroll
        for (int o = 16; o > 0; o >>= 1) m = fmaxf(m, __shfl_xor_sync(0xffffffffu, m, o));
        float sum = 0.f;
        for (int i = lane; i < npad; i += 32) {
            float e = exp2f((sh_p[g][i] - m) * LOG2E);
            sh_p[g][i] = e;
            sum += e;
        }
        #pragma unroll
        for (int o = 16; o > 0; o >>= 1) sum += __shfl_xor_sync(0xffffffffu, sum, o);
        if (lane == 0) { sh_m[g] = m; sh_s[g] = sum; }
    }
    __syncthreads();

    // ---- Phase 3: partial P@V, coalesced; two passes of 4 blocks, each
    //      staging 8 independent LDG.128 before FMAs. ----
    {
        const int j  = lane & 3;
        const int d0 = (wid << 3) + (lane >> 2);     // 0..63
        const int d1 = d0 + 64;
        const float vnd0 = vnew[(size_t)s * (NUM_KV_HEADS * HEAD_SIZE) + h * HEAD_SIZE + d0];
        const float vnd1 = vnew[(size_t)s * (NUM_KV_HEADS * HEAD_SIZE) + h * HEAD_SIZE + d1];

        float acc0[GRP] = {0.f, 0.f, 0.f, 0.f};
        float acc1[GRP] = {0.f, 0.f, 0.f, 0.f};

        #pragma unroll
        for (int bp = 0; bp < 2; bp++) {
            float4 v0[4], v1[4];
            #pragma unroll
            for (int bb = 0; bb < 4; bb++) {
                const int b  = bp * 4 + bb;
                const int bc = min(b, nblk - 1);      // clamp: sh_p is zero there
                const float* vb = vcache + ((size_t)sh_btab[bc] * NUM_KV_HEADS + h) * 2048;
                v0[bb] = ldcs4(vb + d0 * 16 + j * 4);
                v1[bb] = ldcs4(vb + d1 * 16 + j * 4);
            }
            #pragma unroll
            for (int bb = 0; bb < 4; bb++) {
                const int b   = bp * 4 + bb;
                const int ltj = b * BLK_SZ + j * 4;
                const int o = (L - 1) - (t0 + ltj);   // new-token value override
                if ((unsigned)o < 4u) {
                    if      (o == 0) { v0[bb].x = vnd0; v1[bb].x = vnd1; }
                    else if (o == 1) { v0[bb].y = vnd0; v1[bb].y = vnd1; }
                    else if (o == 2) { v0[bb].z = vnd0; v1[bb].z = vnd1; }
                    else             { v0[bb].w = vnd0; v1[bb].w = vnd1; }
                }
                #pragma unroll
                for (int g = 0; g < GRP; g++) {
                    float4 pr = *(const float4*)&sh_p[g][ltj];
                    acc0[g] += v0[bb].x * pr.x + v0[bb].y * pr.y + v0[bb].z * pr.z + v0[bb].w * pr.w;
                    acc1[g] += v1[bb].x * pr.x + v1[bb].y * pr.y + v1[bb].z * pr.z + v1[bb].w * pr.w;
                }
            }
        }
        // reduce over token quads (lane bits 0-1)
        #pragma unroll
        for (int g = 0; g < GRP; g++) {
            acc0[g] += __shfl_xor_sync(0xffffffffu, acc0[g], 1);
            acc0[g] += __shfl_xor_sync(0xffffffffu, acc0[g], 2);
            acc1[g] += __shfl_xor_sync(0xffffffffu, acc1[g], 1);
            acc1[g] += __shfl_xor_sync(0xffffffffu, acc1[g], 2);
        }
        if (j == 0) {
            #pragma unroll
            for (int g = 0; g < GRP; g++) {
                sh_acc[g][d0] = acc0[g];
                sh_acc[g][d1] = acc1[g];
            }
        }
    }
    __syncthreads();

    // ---- write partials ----
    const size_t base = ((size_t)bx) * (GRP * HEAD_SIZE);
    for (int i = tid; i < GRP * HEAD_SIZE; i += 256)
        g_po[base + i] = sh_acc[i >> 7][i & 127];
    if (tid < GRP) {
        g_pm[(size_t)bx * GRP + tid] = sh_m[tid];
        g_ps[(size_t)bx * GRP + tid] = sh_s[tid];
    }

    // ---- fused combine: last CTA for (s,h) finalizes ----
    __threadfence();
    if (tid == 0) {
        int old = atomicAdd(&g_cnt[sh], 1);
        sh_win = (old == np - 1);
        if (sh_win) g_cnt[sh] = 0;   // self-reset for graph replay
    }
    __syncthreads();
    if (!sh_win) return;
    __threadfence();                  // acquire: see all partitions' partials

    // one warp computes combine weights: lane = g + 4*pp
    if (wid == 0) {
        const int g  = lane & 3;
        const int pp = lane >> 2;
        const bool act = (pp < np);
        const size_t idx = ((size_t)sh * MAXP + pp) * GRP + g;
        float m  = act ? g_pm[idx] : -1e30f;
        float M = m;
        #pragma unroll
        for (int o = 4; o < 32; o <<= 1) M = fmaxf(M, __shfl_xor_sync(0xffffffffu, M, o));
        float w  = act ? exp2f((m - M) * LOG2E) : 0.f;
        float den = act ? w * g_ps[idx] : 0.f;
        #pragma unroll
        for (int o = 4; o < 32; o <<= 1) den += __shfl_xor_sync(0xffffffffu, den, o);
        sh_w[pp][g] = w / den;
    }
    __syncthreads();

    for (int i = tid; i < GRP * HEAD_SIZE; i += 256) {
        const int g = i >> 7, d = i & 127;
        float acc = 0.f;
        for (int pp = 0; pp < np; pp++)
            acc += sh_w[pp][g] * g_po[((size_t)sh * MAXP + pp) * (GRP * HEAD_SIZE) + i];
        out[(size_t)s * (NUM_HEADS * HEAD_SIZE) + (h * GRP + g) * HEAD_SIZE + d] = acc;
    }
}

extern "C" void kernel_launch(void* const* d_in, const int* in_sizes, int n_in,
                              void* d_out, int out_size)
{
    const float* query       = (const float*)d_in[0];
    const float* key         = (const float*)d_in[1];
    const float* value       = (const float*)d_in[2];
    const float* key_cache   = (const float*)d_in[3];
    const float* value_cache = (const float*)d_in[4];
    const int*   block_tab   = (const int*)d_in[5];
    const int*   ctx_lens    = (const int*)d_in[6];
    float* out = (float*)d_out;

    paged_attn_split<<<NUM_SEQS * NUM_KV_HEADS * MAXP, 256>>>(
        query, key, value, key_cache, value_cache, block_tab, ctx_lens, out);
}